// round 1
// baseline (speedup 1.0000x reference)
#include <cuda_runtime.h>
#include <cuda_bf16.h>
#include <cstdint>

// Problem constants
#define BATCH 2
#define SEQ   2048
#define DMODEL 1024
#define NHEAD 16
#define DHEAD 64
#define BH    (BATCH * NHEAD)       // 32
#define MROWS (BATCH * SEQ)         // 4096
#define QKVN  (3 * DMODEL)          // 3072

// Scratch (device globals; no runtime allocation allowed)
__device__ float g_q[BH * SEQ * DHEAD];   // [bh][n][d]
__device__ float g_k[BH * SEQ * DHEAD];
__device__ float g_v[BH * SEQ * DHEAD];
__device__ float g_y[MROWS * DMODEL];     // [b*n][dmodel]

// ---------------------------------------------------------------------------
// SGEMM tile config: 128x128 block tile, BK=16, 256 threads, 8x8 per thread
// ---------------------------------------------------------------------------
#define BM 128
#define BN 128
#define BKK 16

// Kernel 1: qkv = x @ Wqkv + bqkv, scattered into g_q/g_k/g_v with head layout
__global__ __launch_bounds__(256) void qkv_gemm_kernel(
    const float* __restrict__ A,     // x [4096, 1024]
    const float* __restrict__ B,     // Wqkv [1024, 3072]
    const float* __restrict__ bias)  // [3072]
{
    __shared__ float As[BKK][BM];
    __shared__ float Bs[BKK][BN];

    const int tid = threadIdx.x;
    const int m0 = blockIdx.y * BM;
    const int n0 = blockIdx.x * BN;
    const int ty = tid >> 4;          // 0..15
    const int tx = tid & 15;          // 0..15

    const int K = DMODEL;
    const int NN = QKVN;

    const int arow = tid >> 2;          // 0..63
    const int acol = (tid & 3) * 4;     // 0,4,8,12
    const int brow = tid >> 5;          // 0..7
    const int bcol = (tid & 31) * 4;    // 0..124

    float acc[8][8] = {};

    for (int k0 = 0; k0 < K; k0 += BKK) {
#pragma unroll
        for (int r = 0; r < 2; r++) {
            float4 a = *(const float4*)&A[(size_t)(m0 + arow + r * 64) * K + k0 + acol];
            As[acol + 0][arow + r * 64] = a.x;
            As[acol + 1][arow + r * 64] = a.y;
            As[acol + 2][arow + r * 64] = a.z;
            As[acol + 3][arow + r * 64] = a.w;
        }
#pragma unroll
        for (int r = 0; r < 2; r++) {
            *(float4*)&Bs[brow + r * 8][bcol] =
                *(const float4*)&B[(size_t)(k0 + brow + r * 8) * NN + n0 + bcol];
        }
        __syncthreads();

#pragma unroll
        for (int k = 0; k < BKK; k++) {
            float af[8], bf[8];
            *(float4*)&af[0] = *(const float4*)&As[k][ty * 8];
            *(float4*)&af[4] = *(const float4*)&As[k][ty * 8 + 4];
            *(float4*)&bf[0] = *(const float4*)&Bs[k][tx * 8];
            *(float4*)&bf[4] = *(const float4*)&Bs[k][tx * 8 + 4];
#pragma unroll
            for (int i = 0; i < 8; i++)
#pragma unroll
                for (int j = 0; j < 8; j++)
                    acc[i][j] += af[i] * bf[j];
        }
        __syncthreads();
    }

    // epilogue: bias + scatter to per-head layout
#pragma unroll
    for (int i = 0; i < 8; i++) {
        const int m = m0 + ty * 8 + i;
        const int b = m >> 11;            // /2048
        const int nq = m & 2047;
#pragma unroll
        for (int j = 0; j < 8; j++) {
            const int n = n0 + tx * 8 + j;
            const float v = acc[i][j] + bias[n];
            const int sel = n >> 10;      // 0:q 1:k 2:v
            const int d0 = n & 1023;
            const int h = d0 >> 6;
            const int dd = d0 & 63;
            float* dst = (sel == 0) ? g_q : (sel == 1) ? g_k : g_v;
            dst[((size_t)(b * NHEAD + h) * SEQ + nq) * DHEAD + dd] = v;
        }
    }
}

// Kernel 3: out = y @ Wproj + bproj
__global__ __launch_bounds__(256) void proj_gemm_kernel(
    const float* __restrict__ B,     // Wproj [1024, 1024]
    const float* __restrict__ bias,  // [1024]
    float* __restrict__ out)         // [4096, 1024]
{
    __shared__ float As[BKK][BM];
    __shared__ float Bs[BKK][BN];

    const float* A = g_y;
    const int tid = threadIdx.x;
    const int m0 = blockIdx.y * BM;
    const int n0 = blockIdx.x * BN;
    const int ty = tid >> 4;
    const int tx = tid & 15;

    const int K = DMODEL;
    const int NN = DMODEL;

    const int arow = tid >> 2;
    const int acol = (tid & 3) * 4;
    const int brow = tid >> 5;
    const int bcol = (tid & 31) * 4;

    float acc[8][8] = {};

    for (int k0 = 0; k0 < K; k0 += BKK) {
#pragma unroll
        for (int r = 0; r < 2; r++) {
            float4 a = *(const float4*)&A[(size_t)(m0 + arow + r * 64) * K + k0 + acol];
            As[acol + 0][arow + r * 64] = a.x;
            As[acol + 1][arow + r * 64] = a.y;
            As[acol + 2][arow + r * 64] = a.z;
            As[acol + 3][arow + r * 64] = a.w;
        }
#pragma unroll
        for (int r = 0; r < 2; r++) {
            *(float4*)&Bs[brow + r * 8][bcol] =
                *(const float4*)&B[(size_t)(k0 + brow + r * 8) * NN + n0 + bcol];
        }
        __syncthreads();

#pragma unroll
        for (int k = 0; k < BKK; k++) {
            float af[8], bf[8];
            *(float4*)&af[0] = *(const float4*)&As[k][ty * 8];
            *(float4*)&af[4] = *(const float4*)&As[k][ty * 8 + 4];
            *(float4*)&bf[0] = *(const float4*)&Bs[k][tx * 8];
            *(float4*)&bf[4] = *(const float4*)&Bs[k][tx * 8 + 4];
#pragma unroll
            for (int i = 0; i < 8; i++)
#pragma unroll
                for (int j = 0; j < 8; j++)
                    acc[i][j] += af[i] * bf[j];
        }
        __syncthreads();
    }

#pragma unroll
    for (int i = 0; i < 8; i++) {
        const int m = m0 + ty * 8 + i;
#pragma unroll
        for (int j = 0; j < 8; j += 4) {
            const int n = n0 + tx * 8 + j;
            float4 v;
            v.x = acc[i][j + 0] + bias[n + 0];
            v.y = acc[i][j + 1] + bias[n + 1];
            v.z = acc[i][j + 2] + bias[n + 2];
            v.w = acc[i][j + 3] + bias[n + 3];
            *(float4*)&out[(size_t)m * DMODEL + n] = v;
        }
    }
}

// ---------------------------------------------------------------------------
// Kernel 2: flash attention, fp32. Block = one (bh, 64-query tile).
// 256 threads: (tq, tk) = (tid/16, tid%16). Each thread: 4x4 S frag, 4x4 O frag.
// Smem: Qs (d-major), KPs (K d-major, then reused as P q-major), Vs (k-major).
// Exactly 48KB static smem.
// ---------------------------------------------------------------------------
__global__ __launch_bounds__(256) void attn_kernel()
{
    __shared__ float Qs[64 * 64];   // [d][q]
    __shared__ float KPs[64 * 64];  // K: [d][k] ; later P: [q][k]
    __shared__ float Vs[64 * 64];   // [k][d]

    const int tid = threadIdx.x;
    const int tq = tid >> 4;        // 0..15 query group
    const int tk = tid & 15;        // 0..15 key/d group
    const int qt = blockIdx.x;      // query tile
    const int bh = blockIdx.y;      // batch*head

    const float* Qg = g_q + (size_t)bh * SEQ * DHEAD;
    const float* Kg = g_k + (size_t)bh * SEQ * DHEAD;
    const float* Vg = g_v + (size_t)bh * SEQ * DHEAD;
    const int q0 = qt * 64;

    const int lrow = tid >> 4;          // 0..15
    const int lcol = (tid & 15) * 4;    // 0..60

    // Load Q tile transposed with softmax scale folded in
#pragma unroll
    for (int r = 0; r < 4; r++) {
        const int row = r * 16 + lrow;
        float4 v = *(const float4*)&Qg[(size_t)(q0 + row) * DHEAD + lcol];
        Qs[(lcol + 0) * 64 + row] = v.x * 0.125f;
        Qs[(lcol + 1) * 64 + row] = v.y * 0.125f;
        Qs[(lcol + 2) * 64 + row] = v.z * 0.125f;
        Qs[(lcol + 3) * 64 + row] = v.w * 0.125f;
    }

    float o[4][4] = {};
    float m_i[4], l_i[4];
#pragma unroll
    for (int i = 0; i < 4; i++) { m_i[i] = -1e30f; l_i[i] = 0.f; }

    for (int kt = 0; kt < SEQ / 64; kt++) {
        __syncthreads();   // prior PV done (and Q store fenced on first iter)
        const int k0 = kt * 64;
#pragma unroll
        for (int r = 0; r < 4; r++) {
            const int row = r * 16 + lrow;
            float4 kv = *(const float4*)&Kg[(size_t)(k0 + row) * DHEAD + lcol];
            KPs[(lcol + 0) * 64 + row] = kv.x;
            KPs[(lcol + 1) * 64 + row] = kv.y;
            KPs[(lcol + 2) * 64 + row] = kv.z;
            KPs[(lcol + 3) * 64 + row] = kv.w;
            *(float4*)&Vs[row * 64 + lcol] =
                *(const float4*)&Vg[(size_t)(k0 + row) * DHEAD + lcol];
        }
        __syncthreads();

        // S = (Q*scale) @ K^T  (4x4 fragment per thread)
        float s[4][4] = {};
#pragma unroll 8
        for (int kk = 0; kk < 64; kk++) {
            float4 qv = *(const float4*)&Qs[kk * 64 + tq * 4];
            float4 kv = *(const float4*)&KPs[kk * 64 + tk * 4];
            s[0][0] += qv.x * kv.x; s[0][1] += qv.x * kv.y; s[0][2] += qv.x * kv.z; s[0][3] += qv.x * kv.w;
            s[1][0] += qv.y * kv.x; s[1][1] += qv.y * kv.y; s[1][2] += qv.y * kv.z; s[1][3] += qv.y * kv.w;
            s[2][0] += qv.z * kv.x; s[2][1] += qv.z * kv.y; s[2][2] += qv.z * kv.z; s[2][3] += qv.z * kv.w;
            s[3][0] += qv.w * kv.x; s[3][1] += qv.w * kv.y; s[3][2] += qv.w * kv.z; s[3][3] += qv.w * kv.w;
        }

        // online softmax update (16-lane group reductions)
#pragma unroll
        for (int i = 0; i < 4; i++) {
            float mt = fmaxf(fmaxf(s[i][0], s[i][1]), fmaxf(s[i][2], s[i][3]));
#pragma unroll
            for (int off = 8; off; off >>= 1)
                mt = fmaxf(mt, __shfl_xor_sync(0xffffffffu, mt, off, 16));
            const float mnew = fmaxf(m_i[i], mt);
            const float corr = __expf(m_i[i] - mnew);
            m_i[i] = mnew;
            float sum = 0.f;
#pragma unroll
            for (int j = 0; j < 4; j++) {
                s[i][j] = __expf(s[i][j] - mnew);
                sum += s[i][j];
            }
#pragma unroll
            for (int off = 8; off; off >>= 1)
                sum += __shfl_xor_sync(0xffffffffu, sum, off, 16);
            l_i[i] = l_i[i] * corr + sum;
#pragma unroll
            for (int j = 0; j < 4; j++) o[i][j] *= corr;
        }

        __syncthreads();   // all S reads of KPs done; safe to overwrite with P
#pragma unroll
        for (int i = 0; i < 4; i++) {
            float4 pv = make_float4(s[i][0], s[i][1], s[i][2], s[i][3]);
            *(float4*)&KPs[(tq * 4 + i) * 64 + tk * 4] = pv;   // P [q][k]
        }
        __syncthreads();

        // O += P @ V   (tk now indexes d)
#pragma unroll 8
        for (int kk = 0; kk < 64; kk++) {
            float4 vv = *(const float4*)&Vs[kk * 64 + tk * 4];
            const float p0 = KPs[(tq * 4 + 0) * 64 + kk];
            const float p1 = KPs[(tq * 4 + 1) * 64 + kk];
            const float p2 = KPs[(tq * 4 + 2) * 64 + kk];
            const float p3 = KPs[(tq * 4 + 3) * 64 + kk];
            o[0][0] += p0 * vv.x; o[0][1] += p0 * vv.y; o[0][2] += p0 * vv.z; o[0][3] += p0 * vv.w;
            o[1][0] += p1 * vv.x; o[1][1] += p1 * vv.y; o[1][2] += p1 * vv.z; o[1][3] += p1 * vv.w;
            o[2][0] += p2 * vv.x; o[2][1] += p2 * vv.y; o[2][2] += p2 * vv.z; o[2][3] += p2 * vv.w;
            o[3][0] += p3 * vv.x; o[3][1] += p3 * vv.y; o[3][2] += p3 * vv.z; o[3][3] += p3 * vv.w;
        }
    }

    // epilogue: normalize and write to y in [b][n][h*64+d] layout
    const int b = bh >> 4;
    const int h = bh & 15;
#pragma unroll
    for (int i = 0; i < 4; i++) {
        const float inv = 1.f / l_i[i];
        float4 ov = make_float4(o[i][0] * inv, o[i][1] * inv, o[i][2] * inv, o[i][3] * inv);
        const int q = q0 + tq * 4 + i;
        *(float4*)&g_y[((size_t)(b * SEQ + q)) * DMODEL + h * DHEAD + tk * 4] = ov;
    }
}

// ---------------------------------------------------------------------------
extern "C" void kernel_launch(void* const* d_in, const int* in_sizes, int n_in,
                              void* d_out, int out_size)
{
    const float* x     = (const float*)d_in[0];   // [2,2048,1024]
    const float* Wqkv  = (const float*)d_in[1];   // [1024,3072]
    const float* bqkv  = (const float*)d_in[2];   // [3072]
    const float* Wproj = (const float*)d_in[3];   // [1024,1024]
    const float* bproj = (const float*)d_in[4];   // [1024]
    float* out = (float*)d_out;

    // 1) QKV projection + head scatter
    {
        dim3 grid(QKVN / BN, MROWS / BM);   // (24, 32)
        qkv_gemm_kernel<<<grid, 256>>>(x, Wqkv, bqkv);
    }
    // 2) attention
    {
        dim3 grid(SEQ / 64, BH);            // (32, 32)
        attn_kernel<<<grid, 256>>>();
    }
    // 3) output projection
    {
        dim3 grid(DMODEL / BN, MROWS / BM); // (8, 32)
        proj_gemm_kernel<<<grid, 256>>>(Wproj, bproj, out);
    }
}

// round 5
// speedup vs baseline: 2.8661x; 2.8661x over previous
#include <cuda_runtime.h>
#include <cuda_bf16.h>
#include <cstdint>

// Problem constants
#define BATCH 2
#define SEQ   2048
#define DMODEL 1024
#define NHEAD 16
#define DHEAD 64
#define BH    (BATCH * NHEAD)       // 32
#define MROWS (BATCH * SEQ)         // 4096
#define QKVN  (3 * DMODEL)          // 3072

// Scratch (device globals; no runtime allocation allowed)
__device__ float g_q[BH * SEQ * DHEAD];   // [bh][n][d]
__device__ float g_k[BH * SEQ * DHEAD];
__device__ float g_v[BH * SEQ * DHEAD];
__device__ float g_y[MROWS * DMODEL];     // [b*n][dmodel]
__device__ float g_wqkvT[QKVN * DMODEL];  // Wqkv^T [3072][1024] (tf32-rounded)
__device__ float g_wprojT[DMODEL * DMODEL];

// ---------------------------------------------------------------------------
__device__ __forceinline__ float tf32r(float v) {
    float r;
    asm("cvt.rna.tf32.f32 %0, %1;" : "=f"(r) : "f"(v));
    return r;
}

// m16n8k8 tf32 MMA: D = A*B + D (fp32 accumulate). a/b are tf32 bit patterns.
__device__ __forceinline__ void mma_tf32(float c[4],
                                         uint32_t a0, uint32_t a1, uint32_t a2, uint32_t a3,
                                         uint32_t b0, uint32_t b1) {
    asm volatile(
        "mma.sync.aligned.m16n8k8.row.col.f32.tf32.tf32.f32 "
        "{%0,%1,%2,%3}, {%4,%5,%6,%7}, {%8,%9}, {%0,%1,%2,%3};"
        : "+f"(c[0]), "+f"(c[1]), "+f"(c[2]), "+f"(c[3])
        : "r"(a0), "r"(a1), "r"(a2), "r"(a3), "r"(b0), "r"(b1));
}

// ---------------------------------------------------------------------------
// Transpose + tf32-round: W [rows, cols] -> WT [cols, rows]
// ---------------------------------------------------------------------------
__global__ __launch_bounds__(256) void transpose_tf32_kernel(
    const float* __restrict__ W, float* __restrict__ WT, int rows, int cols)
{
    __shared__ float t[32][33];
    const int x = blockIdx.x * 32 + threadIdx.x;
    const int y0 = blockIdx.y * 32;
#pragma unroll
    for (int i = threadIdx.y; i < 32; i += 8)
        t[i][threadIdx.x] = W[(size_t)(y0 + i) * cols + x];
    __syncthreads();
    const int ox = y0 + threadIdx.x;
    const int oy0 = blockIdx.x * 32;
#pragma unroll
    for (int i = threadIdx.y; i < 32; i += 8)
        WT[(size_t)(oy0 + i) * rows + ox] = tf32r(t[threadIdx.x][i]);
}

// ---------------------------------------------------------------------------
// tf32 mma.sync GEMM: C[128 x 128] tile = A[m0:,1024] @ BT[n0:,1024]^T + bias
// 256 threads = 8 warps; warp tile 64m x 32n; BK=32, ping-pong smem.
// mode 0: qkv scatter into g_q/g_k/g_v; mode 1: plain row-major out
// ---------------------------------------------------------------------------
#define GK 1024
#define GBK 32
#define APAD 36   // 32 + 4 words per row

__device__ __forceinline__ void gemm_stage(
    float* __restrict__ sA, float* __restrict__ sB,
    const float* __restrict__ A, const float* __restrict__ BT,
    int m0, int n0, int k0, int tid)
{
    const int c4 = (tid & 7) * 4;     // k offset
    const int r0 = tid >> 3;          // 0..31
#pragma unroll
    for (int r = 0; r < 4; r++) {
        const int row = r0 + r * 32;
        float4 va = *(const float4*)&A[(size_t)(m0 + row) * GK + k0 + c4];
        va.x = tf32r(va.x); va.y = tf32r(va.y); va.z = tf32r(va.z); va.w = tf32r(va.w);
        *(float4*)&sA[row * APAD + c4] = va;
        float4 vb = *(const float4*)&BT[(size_t)(n0 + row) * GK + k0 + c4];
        vb.x = tf32r(vb.x); vb.y = tf32r(vb.y); vb.z = tf32r(vb.z); vb.w = tf32r(vb.w);
        *(float4*)&sB[row * APAD + c4] = vb;
    }
}

__global__ __launch_bounds__(256) void tc_gemm_kernel(
    const float* __restrict__ A,      // [M, 1024] row-major
    const float* __restrict__ BT,     // [N, 1024] row-major (pre-rounded)
    const float* __restrict__ bias,   // [N]
    float* __restrict__ out,          // mode 1 only
    int mode)
{
    extern __shared__ float sm[];
    float* sA[2] = { sm,              sm + 128 * APAD };
    float* sB[2] = { sm + 2*128*APAD, sm + 3*128*APAD };

    const int tid = threadIdx.x;
    const int wid = tid >> 5;
    const int lane = tid & 31;
    const int gid = lane >> 2;     // 0..7
    const int tig = lane & 3;      // 0..3
    const int mw = (wid & 1) * 64;
    const int nw = (wid >> 1) * 32;
    const int m0 = blockIdx.y * 128;
    const int n0 = blockIdx.x * 128;

    float C[4][4][4] = {};   // [mtile][ntile][c0..c3]

    gemm_stage(sA[0], sB[0], A, BT, m0, n0, 0, tid);
    __syncthreads();

    for (int i = 0; i < GK / GBK; i++) {
        const int p = i & 1;
        if (i + 1 < GK / GBK)
            gemm_stage(sA[p ^ 1], sB[p ^ 1], A, BT, m0, n0, (i + 1) * GBK, tid);

        const float* a_s = sA[p];
        const float* b_s = sB[p];
#pragma unroll
        for (int kk = 0; kk < 4; kk++) {
            const int kb = kk * 8;
            uint32_t af[4][4], bf[4][2];
#pragma unroll
            for (int mi = 0; mi < 4; mi++) {
                const int rb = (mw + mi * 16 + gid) * APAD + kb;
                af[mi][0] = __float_as_uint(a_s[rb + tig]);
                af[mi][1] = __float_as_uint(a_s[rb + 8 * APAD + tig]);
                af[mi][2] = __float_as_uint(a_s[rb + tig + 4]);
                af[mi][3] = __float_as_uint(a_s[rb + 8 * APAD + tig + 4]);
            }
#pragma unroll
            for (int nj = 0; nj < 4; nj++) {
                const int rb = (nw + nj * 8 + gid) * APAD + kb;
                bf[nj][0] = __float_as_uint(b_s[rb + tig]);
                bf[nj][1] = __float_as_uint(b_s[rb + tig + 4]);
            }
#pragma unroll
            for (int mi = 0; mi < 4; mi++)
#pragma unroll
                for (int nj = 0; nj < 4; nj++)
                    mma_tf32(C[mi][nj], af[mi][0], af[mi][1], af[mi][2], af[mi][3],
                             bf[nj][0], bf[nj][1]);
        }
        __syncthreads();
    }

    // Epilogue
#pragma unroll
    for (int mi = 0; mi < 4; mi++) {
#pragma unroll
        for (int rr = 0; rr < 2; rr++) {
            const int m = m0 + mw + mi * 16 + gid + rr * 8;
#pragma unroll
            for (int nj = 0; nj < 4; nj++) {
                const int n = n0 + nw + nj * 8 + 2 * tig;
                float2 v;
                v.x = C[mi][nj][rr * 2 + 0] + bias[n];
                v.y = C[mi][nj][rr * 2 + 1] + bias[n + 1];
                if (mode == 0) {
                    const int b = m >> 11;
                    const int nq = m & 2047;
                    const int sel = n >> 10;
                    const int h = (n & 1023) >> 6;
                    const int dd = n & 63;
                    float* dst = (sel == 0) ? g_q : (sel == 1) ? g_k : g_v;
                    *(float2*)&dst[((size_t)((b << 4) + h) * SEQ + nq) * DHEAD + dd] = v;
                } else {
                    *(float2*)&out[(size_t)m * DMODEL + n] = v;
                }
            }
        }
    }
}

// ---------------------------------------------------------------------------
// Flash attention with tf32 mma.sync. Block = (bh, 64-q tile), 128 threads.
// Warp w owns q rows [w*16, w*16+16). Keys tiled by 64, d = 64.
// Dyn smem: Qs/Ks/Vs/Ps each [64][68] floats = 69632 B.
// ---------------------------------------------------------------------------
#define SPAD 68

__global__ __launch_bounds__(128) void attn_tc_kernel()
{
    extern __shared__ float sm[];
    float* Qs = sm;                  // [q][d]
    float* Ks = sm + 64 * SPAD;      // [key][d]
    float* Vs = sm + 2 * 64 * SPAD;  // [key][d]
    float* Ps = sm + 3 * 64 * SPAD;  // [q][key]

    const int tid = threadIdx.x;
    const int wid = tid >> 5;
    const int lane = tid & 31;
    const int gid = lane >> 2;
    const int tig = lane & 3;
    const int qb = wid * 16;

    const int qt = blockIdx.x;
    const int bh = blockIdx.y;
    const int q0 = qt * 64;

    const float* Qg = g_q + (size_t)bh * SEQ * DHEAD;
    const float* Kg = g_k + (size_t)bh * SEQ * DHEAD;
    const float* Vg = g_v + (size_t)bh * SEQ * DHEAD;

    // Load Q once (scale + tf32 round). 128 threads = 8 rows x 16 float4 cols
    // per pass; 8 passes of row-stride 8 cover all 64 rows.
    {
        const int row = tid >> 4;            // 0..7
        const int c4 = (tid & 15) * 4;
#pragma unroll
        for (int r = 0; r < 8; r++) {
            const int rr = row + r * 8;
            float4 v = *(const float4*)&Qg[(size_t)(q0 + rr) * DHEAD + c4];
            v.x = tf32r(v.x * 0.125f); v.y = tf32r(v.y * 0.125f);
            v.z = tf32r(v.z * 0.125f); v.w = tf32r(v.w * 0.125f);
            *(float4*)&Qs[rr * SPAD + c4] = v;
        }
    }

    float O[8][4] = {};
    float m_i[2] = { -1e30f, -1e30f };
    float l_i[2] = { 0.f, 0.f };

    for (int kt = 0; kt < SEQ / 64; kt++) {
        __syncthreads();   // prev PV reads of Vs/Ps done; Q visible on first iter
        {
            const int row = tid >> 4;        // 0..7
            const int c4 = (tid & 15) * 4;
            const int k0 = kt * 64;
#pragma unroll
            for (int r = 0; r < 8; r++) {
                const int rr = row + r * 8;
                float4 kv = *(const float4*)&Kg[(size_t)(k0 + rr) * DHEAD + c4];
                kv.x = tf32r(kv.x); kv.y = tf32r(kv.y); kv.z = tf32r(kv.z); kv.w = tf32r(kv.w);
                *(float4*)&Ks[rr * SPAD + c4] = kv;
                float4 vv = *(const float4*)&Vg[(size_t)(k0 + rr) * DHEAD + c4];
                vv.x = tf32r(vv.x); vv.y = tf32r(vv.y); vv.z = tf32r(vv.z); vv.w = tf32r(vv.w);
                *(float4*)&Vs[rr * SPAD + c4] = vv;
            }
        }
        __syncthreads();

        // S = Q @ K^T : 8 ntiles (keys) x 8 ksteps (d)
        float S[8][4] = {};
#pragma unroll
        for (int kk = 0; kk < 8; kk++) {
            const int kb = kk * 8;
            const int rb = (qb + gid) * SPAD + kb;
            uint32_t a0 = __float_as_uint(Qs[rb + tig]);
            uint32_t a1 = __float_as_uint(Qs[rb + 8 * SPAD + tig]);
            uint32_t a2 = __float_as_uint(Qs[rb + tig + 4]);
            uint32_t a3 = __float_as_uint(Qs[rb + 8 * SPAD + tig + 4]);
#pragma unroll
            for (int j = 0; j < 8; j++) {
                const int nb = (j * 8 + gid) * SPAD + kb;
                uint32_t b0 = __float_as_uint(Ks[nb + tig]);
                uint32_t b1 = __float_as_uint(Ks[nb + tig + 4]);
                mma_tf32(S[j], a0, a1, a2, a3, b0, b1);
            }
        }

        // online softmax on fragment rows (gid rr=0, gid+8 rr=1)
#pragma unroll
        for (int rr = 0; rr < 2; rr++) {
            float mx = -1e30f;
#pragma unroll
            for (int j = 0; j < 8; j++)
                mx = fmaxf(mx, fmaxf(S[j][rr * 2], S[j][rr * 2 + 1]));
            mx = fmaxf(mx, __shfl_xor_sync(0xffffffffu, mx, 1));
            mx = fmaxf(mx, __shfl_xor_sync(0xffffffffu, mx, 2));
            const float mnew = fmaxf(m_i[rr], mx);
            const float corr = __expf(m_i[rr] - mnew);
            m_i[rr] = mnew;
            float sum = 0.f;
#pragma unroll
            for (int j = 0; j < 8; j++) {
                float e0 = __expf(S[j][rr * 2] - mnew);
                float e1 = __expf(S[j][rr * 2 + 1] - mnew);
                S[j][rr * 2] = e0; S[j][rr * 2 + 1] = e1;
                sum += e0 + e1;
            }
            sum += __shfl_xor_sync(0xffffffffu, sum, 1);
            sum += __shfl_xor_sync(0xffffffffu, sum, 2);
            l_i[rr] = l_i[rr] * corr + sum;
#pragma unroll
            for (int j = 0; j < 8; j++) {
                O[j][rr * 2] *= corr;
                O[j][rr * 2 + 1] *= corr;
            }
        }

        // write P (tf32) to warp-private rows of Ps
#pragma unroll
        for (int j = 0; j < 8; j++) {
            float2 p0 = make_float2(tf32r(S[j][0]), tf32r(S[j][1]));
            float2 p1 = make_float2(tf32r(S[j][2]), tf32r(S[j][3]));
            *(float2*)&Ps[(qb + gid) * SPAD + j * 8 + 2 * tig] = p0;
            *(float2*)&Ps[(qb + gid + 8) * SPAD + j * 8 + 2 * tig] = p1;
        }
        __syncwarp();

        // O += P @ V : ksteps over keys, ntiles over d
#pragma unroll
        for (int kk = 0; kk < 8; kk++) {
            const int kb = kk * 8;
            const int rb = (qb + gid) * SPAD + kb;
            uint32_t a0 = __float_as_uint(Ps[rb + tig]);
            uint32_t a1 = __float_as_uint(Ps[rb + 8 * SPAD + tig]);
            uint32_t a2 = __float_as_uint(Ps[rb + tig + 4]);
            uint32_t a3 = __float_as_uint(Ps[rb + 8 * SPAD + tig + 4]);
#pragma unroll
            for (int j = 0; j < 8; j++) {
                uint32_t b0 = __float_as_uint(Vs[(kb + tig) * SPAD + j * 8 + gid]);
                uint32_t b1 = __float_as_uint(Vs[(kb + tig + 4) * SPAD + j * 8 + gid]);
                mma_tf32(O[j], a0, a1, a2, a3, b0, b1);
            }
        }
    }

    // epilogue: normalize, write to y [b][n][h*64+d]
    const int b = bh >> 4;
    const int h = bh & 15;
    const float inv0 = 1.f / l_i[0];
    const float inv1 = 1.f / l_i[1];
    const int qg0 = q0 + qb + gid;
#pragma unroll
    for (int j = 0; j < 8; j++) {
        const int d = h * 64 + j * 8 + 2 * tig;
        float2 v0 = make_float2(O[j][0] * inv0, O[j][1] * inv0);
        float2 v1 = make_float2(O[j][2] * inv1, O[j][3] * inv1);
        *(float2*)&g_y[(size_t)(b * SEQ + qg0) * DMODEL + d] = v0;
        *(float2*)&g_y[(size_t)(b * SEQ + qg0 + 8) * DMODEL + d] = v1;
    }
}

// ---------------------------------------------------------------------------
extern "C" void kernel_launch(void* const* d_in, const int* in_sizes, int n_in,
                              void* d_out, int out_size)
{
    const float* x     = (const float*)d_in[0];   // [2,2048,1024]
    const float* Wqkv  = (const float*)d_in[1];   // [1024,3072]
    const float* bqkv  = (const float*)d_in[2];   // [3072]
    const float* Wproj = (const float*)d_in[3];   // [1024,1024]
    const float* bproj = (const float*)d_in[4];   // [1024]
    float* out = (float*)d_out;

    // Resolve DEVICE addresses of __device__ globals used as host-passed args.
    // (Passing the symbol directly from host code passes the host shadow
    // address — that was the R3/R4 correctness bug for g_y.)
    float* wqkvT;  cudaGetSymbolAddress((void**)&wqkvT, g_wqkvT);
    float* wprojT; cudaGetSymbolAddress((void**)&wprojT, g_wprojT);
    float* yptr;   cudaGetSymbolAddress((void**)&yptr, g_y);

    const int gemm_smem = 4 * 128 * APAD * 4;        // 73728 B
    const int attn_smem = 4 * 64 * SPAD * 4;         // 69632 B
    cudaFuncSetAttribute(tc_gemm_kernel,
                         cudaFuncAttributeMaxDynamicSharedMemorySize, gemm_smem);
    cudaFuncSetAttribute(attn_tc_kernel,
                         cudaFuncAttributeMaxDynamicSharedMemorySize, attn_smem);

    // 0) transpose + tf32-round weights
    {
        dim3 blk(32, 8);
        transpose_tf32_kernel<<<dim3(QKVN / 32, DMODEL / 32), blk>>>(Wqkv, wqkvT, DMODEL, QKVN);
        transpose_tf32_kernel<<<dim3(DMODEL / 32, DMODEL / 32), blk>>>(Wproj, wprojT, DMODEL, DMODEL);
    }
    // 1) QKV projection + head scatter
    {
        dim3 grid(QKVN / 128, MROWS / 128);   // (24, 32)
        tc_gemm_kernel<<<grid, 256, gemm_smem>>>(x, wqkvT, bqkv, nullptr, 0);
    }
    // 2) attention
    {
        dim3 grid(SEQ / 64, BH);              // (32, 32)
        attn_tc_kernel<<<grid, 128, attn_smem>>>();
    }
    // 3) output projection
    {
        dim3 grid(DMODEL / 128, MROWS / 128); // (8, 32)
        tc_gemm_kernel<<<grid, 256, gemm_smem>>>(yptr, wprojT, bproj, out, 1);
    }
}

// round 6
// speedup vs baseline: 3.4524x; 1.2046x over previous
#include <cuda_runtime.h>
#include <cuda_bf16.h>
#include <cstdint>

// Problem constants
#define BATCH 2
#define SEQ   2048
#define DMODEL 1024
#define NHEAD 16
#define DHEAD 64
#define BH    (BATCH * NHEAD)       // 32
#define MROWS (BATCH * SEQ)         // 4096
#define QKVN  (3 * DMODEL)          // 3072

// Scratch (device globals; no runtime allocation allowed)
__device__ float g_q[BH * SEQ * DHEAD];   // [bh][n][d]
__device__ float g_k[BH * SEQ * DHEAD];
__device__ float g_v[BH * SEQ * DHEAD];
__device__ float g_y[MROWS * DMODEL];     // [b*n][dmodel]
__device__ float g_wqkvT[QKVN * DMODEL];  // Wqkv^T [3072][1024] (tf32-rounded)
__device__ float g_wprojT[DMODEL * DMODEL];

// ---------------------------------------------------------------------------
__device__ __forceinline__ float tf32r(float v) {
    float r;
    asm("cvt.rna.tf32.f32 %0, %1;" : "=f"(r) : "f"(v));
    return r;
}

// m16n8k8 tf32 MMA: D = A*B + D (fp32 accumulate). a/b are tf32 bit patterns.
__device__ __forceinline__ void mma_tf32(float c[4],
                                         uint32_t a0, uint32_t a1, uint32_t a2, uint32_t a3,
                                         uint32_t b0, uint32_t b1) {
    asm volatile(
        "mma.sync.aligned.m16n8k8.row.col.f32.tf32.tf32.f32 "
        "{%0,%1,%2,%3}, {%4,%5,%6,%7}, {%8,%9}, {%0,%1,%2,%3};"
        : "+f"(c[0]), "+f"(c[1]), "+f"(c[2]), "+f"(c[3])
        : "r"(a0), "r"(a1), "r"(a2), "r"(a3), "r"(b0), "r"(b1));
}

// ---------------------------------------------------------------------------
// Transpose + tf32-round: W [rows, cols] -> WT [cols, rows]
// ---------------------------------------------------------------------------
__global__ __launch_bounds__(256) void transpose_tf32_kernel(
    const float* __restrict__ W, float* __restrict__ WT, int rows, int cols)
{
    __shared__ float t[32][33];
    const int x = blockIdx.x * 32 + threadIdx.x;
    const int y0 = blockIdx.y * 32;
#pragma unroll
    for (int i = threadIdx.y; i < 32; i += 8)
        t[i][threadIdx.x] = W[(size_t)(y0 + i) * cols + x];
    __syncthreads();
    const int ox = y0 + threadIdx.x;
    const int oy0 = blockIdx.x * 32;
#pragma unroll
    for (int i = threadIdx.y; i < 32; i += 8)
        WT[(size_t)(oy0 + i) * rows + ox] = tf32r(t[threadIdx.x][i]);
}

// ---------------------------------------------------------------------------
// tf32 mma.sync GEMM: C[128 x 128] tile = A[m0:,1024] @ BT[n0:,1024]^T + bias
// 256 threads = 8 warps; warp tile 64m x 32n; BK=32, ping-pong smem.
// mode 0: qkv scatter into g_q/g_k/g_v; mode 1: plain row-major out
// ---------------------------------------------------------------------------
#define GK 1024
#define GBK 32
#define APAD 36   // 32 + 4 words per row

__device__ __forceinline__ void gemm_stage(
    float* __restrict__ sA, float* __restrict__ sB,
    const float* __restrict__ A, const float* __restrict__ BT,
    int m0, int n0, int k0, int tid)
{
    const int c4 = (tid & 7) * 4;     // k offset
    const int r0 = tid >> 3;          // 0..31
#pragma unroll
    for (int r = 0; r < 4; r++) {
        const int row = r0 + r * 32;
        float4 va = *(const float4*)&A[(size_t)(m0 + row) * GK + k0 + c4];
        va.x = tf32r(va.x); va.y = tf32r(va.y); va.z = tf32r(va.z); va.w = tf32r(va.w);
        *(float4*)&sA[row * APAD + c4] = va;
        float4 vb = *(const float4*)&BT[(size_t)(n0 + row) * GK + k0 + c4];
        vb.x = tf32r(vb.x); vb.y = tf32r(vb.y); vb.z = tf32r(vb.z); vb.w = tf32r(vb.w);
        *(float4*)&sB[row * APAD + c4] = vb;
    }
}

__global__ __launch_bounds__(256) void tc_gemm_kernel(
    const float* __restrict__ A,      // [M, 1024] row-major
    const float* __restrict__ BT,     // [N, 1024] row-major (pre-rounded)
    const float* __restrict__ bias,   // [N]
    float* __restrict__ out,          // mode 1 only
    int mode)
{
    extern __shared__ float sm[];
    float* sA[2] = { sm,              sm + 128 * APAD };
    float* sB[2] = { sm + 2*128*APAD, sm + 3*128*APAD };

    const int tid = threadIdx.x;
    const int wid = tid >> 5;
    const int lane = tid & 31;
    const int gid = lane >> 2;     // 0..7
    const int tig = lane & 3;      // 0..3
    const int mw = (wid & 1) * 64;
    const int nw = (wid >> 1) * 32;
    const int m0 = blockIdx.y * 128;
    const int n0 = blockIdx.x * 128;

    float C[4][4][4] = {};   // [mtile][ntile][c0..c3]

    gemm_stage(sA[0], sB[0], A, BT, m0, n0, 0, tid);
    __syncthreads();

    for (int i = 0; i < GK / GBK; i++) {
        const int p = i & 1;
        if (i + 1 < GK / GBK)
            gemm_stage(sA[p ^ 1], sB[p ^ 1], A, BT, m0, n0, (i + 1) * GBK, tid);

        const float* a_s = sA[p];
        const float* b_s = sB[p];
#pragma unroll
        for (int kk = 0; kk < 4; kk++) {
            const int kb = kk * 8;
            uint32_t af[4][4], bf[4][2];
#pragma unroll
            for (int mi = 0; mi < 4; mi++) {
                const int rb = (mw + mi * 16 + gid) * APAD + kb;
                af[mi][0] = __float_as_uint(a_s[rb + tig]);
                af[mi][1] = __float_as_uint(a_s[rb + 8 * APAD + tig]);
                af[mi][2] = __float_as_uint(a_s[rb + tig + 4]);
                af[mi][3] = __float_as_uint(a_s[rb + 8 * APAD + tig + 4]);
            }
#pragma unroll
            for (int nj = 0; nj < 4; nj++) {
                const int rb = (nw + nj * 8 + gid) * APAD + kb;
                bf[nj][0] = __float_as_uint(b_s[rb + tig]);
                bf[nj][1] = __float_as_uint(b_s[rb + tig + 4]);
            }
#pragma unroll
            for (int mi = 0; mi < 4; mi++)
#pragma unroll
                for (int nj = 0; nj < 4; nj++)
                    mma_tf32(C[mi][nj], af[mi][0], af[mi][1], af[mi][2], af[mi][3],
                             bf[nj][0], bf[nj][1]);
        }
        __syncthreads();
    }

    // Epilogue
#pragma unroll
    for (int mi = 0; mi < 4; mi++) {
#pragma unroll
        for (int rr = 0; rr < 2; rr++) {
            const int m = m0 + mw + mi * 16 + gid + rr * 8;
#pragma unroll
            for (int nj = 0; nj < 4; nj++) {
                const int n = n0 + nw + nj * 8 + 2 * tig;
                float2 v;
                v.x = C[mi][nj][rr * 2 + 0] + bias[n];
                v.y = C[mi][nj][rr * 2 + 1] + bias[n + 1];
                if (mode == 0) {
                    const int b = m >> 11;
                    const int nq = m & 2047;
                    const int sel = n >> 10;
                    const int h = (n & 1023) >> 6;
                    const int dd = n & 63;
                    float* dst = (sel == 0) ? g_q : (sel == 1) ? g_k : g_v;
                    *(float2*)&dst[((size_t)((b << 4) + h) * SEQ + nq) * DHEAD + dd] = v;
                } else {
                    *(float2*)&out[(size_t)m * DMODEL + n] = v;
                }
            }
        }
    }
}

// ---------------------------------------------------------------------------
// Flash attention with tf32 mma.sync. Block = (bh, 64-q tile), 128 threads.
// Warp w owns q rows [w*16, w*16+16). Keys tiled by 64, d = 64.
// v2: Q fragments hoisted to registers; P kept in registers via shuffles
// (no Ps smem); V padded to 72 for conflict-free b-frag loads.
// Dyn smem: Ks[64][68] + Vs[64][72] = 35840 B.
// ---------------------------------------------------------------------------
#define KPAD 68
#define VPAD 72

__global__ __launch_bounds__(128) void attn_tc_kernel()
{
    extern __shared__ float sm[];
    float* Ks = sm;                 // [key][d], pad 68
    float* Vs = sm + 64 * KPAD;     // [key][d], pad 72

    const int tid = threadIdx.x;
    const int wid = tid >> 5;
    const int lane = tid & 31;
    const int gid = lane >> 2;
    const int tig = lane & 3;
    const int qb = wid * 16;

    const int qt = blockIdx.x;
    const int bh = blockIdx.y;
    const int q0 = qt * 64;

    const float* Qg = g_q + (size_t)bh * SEQ * DHEAD;
    const float* Kg = g_k + (size_t)bh * SEQ * DHEAD;
    const float* Vg = g_v + (size_t)bh * SEQ * DHEAD;

    // Hoist Q fragments into registers (once per block lifetime).
    // a-frag layout: a0=(gid,kb+tig) a1=(gid+8,kb+tig) a2=(gid,kb+tig+4) a3=(gid+8,kb+tig+4)
    uint32_t QF[8][4];
    {
        const size_t r0 = (size_t)(q0 + qb + gid) * DHEAD;
        const size_t r1 = (size_t)(q0 + qb + gid + 8) * DHEAD;
#pragma unroll
        for (int kk = 0; kk < 8; kk++) {
            const int kb = kk * 8;
            QF[kk][0] = __float_as_uint(tf32r(Qg[r0 + kb + tig] * 0.125f));
            QF[kk][1] = __float_as_uint(tf32r(Qg[r1 + kb + tig] * 0.125f));
            QF[kk][2] = __float_as_uint(tf32r(Qg[r0 + kb + tig + 4] * 0.125f));
            QF[kk][3] = __float_as_uint(tf32r(Qg[r1 + kb + tig + 4] * 0.125f));
        }
    }

    float O[8][4] = {};
    float m_i[2] = { -1e30f, -1e30f };
    float l_i[2] = { 0.f, 0.f };

    const int psrc0 = (lane & ~3) | (tig >> 1);   // gid*4 + tig/2
    const int psrc1 = psrc0 + 2;
    const bool pe = (tig & 1);

    for (int kt = 0; kt < SEQ / 64; kt++) {
        __syncthreads();   // prior iter's K/V reads done
        {
            const int row = tid >> 4;        // 0..7
            const int c4 = (tid & 15) * 4;
            const int k0 = kt * 64;
#pragma unroll
            for (int r = 0; r < 8; r++) {
                const int rr = row + r * 8;
                float4 kv = *(const float4*)&Kg[(size_t)(k0 + rr) * DHEAD + c4];
                kv.x = tf32r(kv.x); kv.y = tf32r(kv.y); kv.z = tf32r(kv.z); kv.w = tf32r(kv.w);
                *(float4*)&Ks[rr * KPAD + c4] = kv;
                float4 vv = *(const float4*)&Vg[(size_t)(k0 + rr) * DHEAD + c4];
                vv.x = tf32r(vv.x); vv.y = tf32r(vv.y); vv.z = tf32r(vv.z); vv.w = tf32r(vv.w);
                *(float4*)&Vs[rr * VPAD + c4] = vv;
            }
        }
        __syncthreads();

        // S = Q @ K^T : 8 ntiles (keys) x 8 ksteps (d). Q from registers.
        float S[8][4] = {};
#pragma unroll
        for (int kk = 0; kk < 8; kk++) {
            const int kb = kk * 8;
#pragma unroll
            for (int j = 0; j < 8; j++) {
                const int nb = (j * 8 + gid) * KPAD + kb;
                uint32_t b0 = __float_as_uint(Ks[nb + tig]);
                uint32_t b1 = __float_as_uint(Ks[nb + tig + 4]);
                mma_tf32(S[j], QF[kk][0], QF[kk][1], QF[kk][2], QF[kk][3], b0, b1);
            }
        }

        // online softmax on fragment rows (gid rr=0, gid+8 rr=1)
#pragma unroll
        for (int rr = 0; rr < 2; rr++) {
            float mx = -1e30f;
#pragma unroll
            for (int j = 0; j < 8; j++)
                mx = fmaxf(mx, fmaxf(S[j][rr * 2], S[j][rr * 2 + 1]));
            mx = fmaxf(mx, __shfl_xor_sync(0xffffffffu, mx, 1));
            mx = fmaxf(mx, __shfl_xor_sync(0xffffffffu, mx, 2));
            const float mnew = fmaxf(m_i[rr], mx);
            const float corr = __expf(m_i[rr] - mnew);
            m_i[rr] = mnew;
            float sum = 0.f;
#pragma unroll
            for (int j = 0; j < 8; j++) {
                float e0 = __expf(S[j][rr * 2] - mnew);
                float e1 = __expf(S[j][rr * 2 + 1] - mnew);
                S[j][rr * 2] = e0; S[j][rr * 2 + 1] = e1;
                sum += e0 + e1;
            }
            sum += __shfl_xor_sync(0xffffffffu, sum, 1);
            sum += __shfl_xor_sync(0xffffffffu, sum, 2);
            l_i[rr] = l_i[rr] * corr + sum;
#pragma unroll
            for (int j = 0; j < 8; j++) {
                O[j][rr * 2] *= corr;
                O[j][rr * 2 + 1] *= corr;
            }
        }

        // tf32-round P in place (unbiased), then O += P @ V with shuffled
        // a-frags: a-frag col kb+tig lives in S[kk][e] of lane (gid, tig/2).
#pragma unroll
        for (int j = 0; j < 8; j++) {
            S[j][0] = tf32r(S[j][0]); S[j][1] = tf32r(S[j][1]);
            S[j][2] = tf32r(S[j][2]); S[j][3] = tf32r(S[j][3]);
        }

#pragma unroll
        for (int kk = 0; kk < 8; kk++) {
            const int kb = kk * 8;
            float v00 = __shfl_sync(0xffffffffu, S[kk][0], psrc0);
            float v01 = __shfl_sync(0xffffffffu, S[kk][1], psrc0);
            float v10 = __shfl_sync(0xffffffffu, S[kk][2], psrc0);
            float v11 = __shfl_sync(0xffffffffu, S[kk][3], psrc0);
            float w00 = __shfl_sync(0xffffffffu, S[kk][0], psrc1);
            float w01 = __shfl_sync(0xffffffffu, S[kk][1], psrc1);
            float w10 = __shfl_sync(0xffffffffu, S[kk][2], psrc1);
            float w11 = __shfl_sync(0xffffffffu, S[kk][3], psrc1);
            uint32_t a0 = __float_as_uint(pe ? v01 : v00);
            uint32_t a1 = __float_as_uint(pe ? v11 : v10);
            uint32_t a2 = __float_as_uint(pe ? w01 : w00);
            uint32_t a3 = __float_as_uint(pe ? w11 : w10);
#pragma unroll
            for (int j = 0; j < 8; j++) {
                const int nb = j * 8 + gid;
                uint32_t b0 = __float_as_uint(Vs[(kb + tig) * VPAD + nb]);
                uint32_t b1 = __float_as_uint(Vs[(kb + tig + 4) * VPAD + nb]);
                mma_tf32(O[j], a0, a1, a2, a3, b0, b1);
            }
        }
    }

    // epilogue: normalize, write to y [b][n][h*64+d]
    const int b = bh >> 4;
    const int h = bh & 15;
    const float inv0 = 1.f / l_i[0];
    const float inv1 = 1.f / l_i[1];
    const int qg0 = q0 + qb + gid;
#pragma unroll
    for (int j = 0; j < 8; j++) {
        const int d = h * 64 + j * 8 + 2 * tig;
        float2 v0 = make_float2(O[j][0] * inv0, O[j][1] * inv0);
        float2 v1 = make_float2(O[j][2] * inv1, O[j][3] * inv1);
        *(float2*)&g_y[(size_t)(b * SEQ + qg0) * DMODEL + d] = v0;
        *(float2*)&g_y[(size_t)(b * SEQ + qg0 + 8) * DMODEL + d] = v1;
    }
}

// ---------------------------------------------------------------------------
extern "C" void kernel_launch(void* const* d_in, const int* in_sizes, int n_in,
                              void* d_out, int out_size)
{
    const float* x     = (const float*)d_in[0];   // [2,2048,1024]
    const float* Wqkv  = (const float*)d_in[1];   // [1024,3072]
    const float* bqkv  = (const float*)d_in[2];   // [3072]
    const float* Wproj = (const float*)d_in[3];   // [1024,1024]
    const float* bproj = (const float*)d_in[4];   // [1024]
    float* out = (float*)d_out;

    // Resolve DEVICE addresses of __device__ globals used as host-passed args.
    float* wqkvT;  cudaGetSymbolAddress((void**)&wqkvT, g_wqkvT);
    float* wprojT; cudaGetSymbolAddress((void**)&wprojT, g_wprojT);
    float* yptr;   cudaGetSymbolAddress((void**)&yptr, g_y);

    const int gemm_smem = 4 * 128 * APAD * 4;             // 73728 B
    const int attn_smem = (64 * KPAD + 64 * VPAD) * 4;    // 35840 B
    cudaFuncSetAttribute(tc_gemm_kernel,
                         cudaFuncAttributeMaxDynamicSharedMemorySize, gemm_smem);
    cudaFuncSetAttribute(attn_tc_kernel,
                         cudaFuncAttributeMaxDynamicSharedMemorySize, attn_smem);

    // 0) transpose + tf32-round weights
    {
        dim3 blk(32, 8);
        transpose_tf32_kernel<<<dim3(QKVN / 32, DMODEL / 32), blk>>>(Wqkv, wqkvT, DMODEL, QKVN);
        transpose_tf32_kernel<<<dim3(DMODEL / 32, DMODEL / 32), blk>>>(Wproj, wprojT, DMODEL, DMODEL);
    }
    // 1) QKV projection + head scatter
    {
        dim3 grid(QKVN / 128, MROWS / 128);   // (24, 32)
        tc_gemm_kernel<<<grid, 256, gemm_smem>>>(x, wqkvT, bqkv, nullptr, 0);
    }
    // 2) attention
    {
        dim3 grid(SEQ / 64, BH);              // (32, 32)
        attn_tc_kernel<<<grid, 128, attn_smem>>>();
    }
    // 3) output projection
    {
        dim3 grid(DMODEL / 128, MROWS / 128); // (8, 32)
        tc_gemm_kernel<<<grid, 256, gemm_smem>>>(yptr, wprojT, bproj, out, 1);
    }
}